// round 4
// baseline (speedup 1.0000x reference)
#include <cuda_runtime.h>
#include <cuda_bf16.h>

#define N_PTS 100000
#define C_IN 24
#define C_HID 144
#define C_OUT 24
#define KS 9
#define EPS 1e-5f

// ---- scratch (device globals: allocation-free rule) ----
__device__ __align__(16) float g_x1[N_PTS * C_HID];
__device__ __align__(16) float g_x2[N_PTS * C_HID];
__device__ __align__(16) float g_y [N_PTS * C_OUT];

__device__ float g_s1[C_HID], g_q1[C_HID];
__device__ float g_s2[C_HID], g_q2[C_HID];
__device__ float g_s3[C_OUT], g_q3[C_OUT];

__device__ __forceinline__ float relu6f(float x) { return fminf(fmaxf(x, 0.f), 6.f); }

// ---- K1: x1 = feats @ w1 (+ per-channel sum/sumsq); block0 zeroes stage-2 accums ----
#define R1 64
#define T1 288
__global__ void __launch_bounds__(T1) k1_gemm1(const float* __restrict__ feats,
                                               const float* __restrict__ w1) {
    __shared__ __align__(16) float sfT[C_IN][R1];
    __shared__ __align__(16) float sw1[C_IN * C_HID];
    __shared__ __align__(16) float rs[8][C_HID], rq[8][C_HID];

    int tid = threadIdx.x;
    int row0 = blockIdx.x * R1;

    if (blockIdx.x == 0 && tid < C_HID) { g_s2[tid] = 0.f; g_q2[tid] = 0.f; }

    for (int i = tid; i < C_IN * C_HID; i += T1) sw1[i] = w1[i];
    for (int i = tid; i < R1 * C_IN; i += T1) {
        int r = i / C_IN, k = i % C_IN;
        int rr = row0 + r;
        sfT[k][r] = (rr < N_PTS) ? feats[rr * C_IN + k] : 0.f;
    }
    __syncthreads();

    int c4 = tid % 36, rg = tid / 36;
    int cb = c4 * 4;
    float4 acc[8];
#pragma unroll
    for (int j = 0; j < 8; j++) acc[j] = make_float4(0.f, 0.f, 0.f, 0.f);

#pragma unroll
    for (int k = 0; k < C_IN; k++) {
        float4 w  = *(const float4*)&sw1[k * C_HID + cb];
        float4 xa = *(const float4*)&sfT[k][rg * 8];
        float4 xb = *(const float4*)&sfT[k][rg * 8 + 4];
        float xr[8] = {xa.x, xa.y, xa.z, xa.w, xb.x, xb.y, xb.z, xb.w};
#pragma unroll
        for (int j = 0; j < 8; j++) {
            acc[j].x = fmaf(w.x, xr[j], acc[j].x);
            acc[j].y = fmaf(w.y, xr[j], acc[j].y);
            acc[j].z = fmaf(w.z, xr[j], acc[j].z);
            acc[j].w = fmaf(w.w, xr[j], acc[j].w);
        }
    }

    float4 s4 = make_float4(0.f, 0.f, 0.f, 0.f), q4 = s4;
#pragma unroll
    for (int j = 0; j < 8; j++) {
        int rr = row0 + rg * 8 + j;
        if (rr < N_PTS) *(float4*)&g_x1[(size_t)rr * C_HID + cb] = acc[j];
        s4.x += acc[j].x; s4.y += acc[j].y; s4.z += acc[j].z; s4.w += acc[j].w;
        q4.x += acc[j].x * acc[j].x; q4.y += acc[j].y * acc[j].y;
        q4.z += acc[j].z * acc[j].z; q4.w += acc[j].w * acc[j].w;
    }
    *(float4*)&rs[rg][cb] = s4;
    *(float4*)&rq[rg][cb] = q4;
    __syncthreads();
    if (tid < C_HID) {
        float s = 0.f, q = 0.f;
#pragma unroll
        for (int g = 0; g < 8; g++) { s += rs[g][tid]; q += rq[g][tid]; }
        atomicAdd(&g_s1[tid], s);
        atomicAdd(&g_q1[tid], q);
    }
}

// ---- K3: channelwise 3x3 sparse conv (compacted gather) + BN2 stats ----
// Per-block: compute bn1 scale/shift from raw sums; compact valid neighbors per row.
#define R3 32
#define T3 288   // 72 channel-groups (float2) x 4 row-lanes
__global__ void __launch_bounds__(T3) k3_conv(const float* __restrict__ w2,
                                              const int* __restrict__ in_idx,
                                              const float* __restrict__ g1,
                                              const float* __restrict__ b1) {
    __shared__ float ssc[C_HID], ssh[C_HID];
    __shared__ __align__(8) float sw2[KS * C_HID];
    __shared__ int plist[R3][KS];
    __shared__ int cnt[R3];
    __shared__ __align__(8) float rs[4][C_HID], rq[4][C_HID];

    int tid = threadIdx.x;
    int row0 = blockIdx.x * R3;      // N_PTS % R3 == 0

    if (blockIdx.x == 0 && tid < C_OUT) { g_s3[tid] = 0.f; g_q3[tid] = 0.f; }

    for (int i = tid; i < KS * C_HID; i += T3) sw2[i] = w2[i];
    if (tid < C_HID) {
        float m = g_s1[tid] * (1.0f / N_PTS);
        float v = g_q1[tid] * (1.0f / N_PTS) - m * m;
        float sc = g1[tid] * rsqrtf(v + EPS);
        ssc[tid] = sc;
        ssh[tid] = b1[tid] - m * sc;
    }
    if (tid < R3) {
        int c = 0;
#pragma unroll
        for (int k = 0; k < KS; k++) {
            int nbr = in_idx[k * N_PTS + row0 + tid];
            if (nbr < N_PTS) plist[tid][c++] = (nbr << 4) | k;
        }
        cnt[tid] = c;
    }
    __syncthreads();

    int cg = tid % 72, rl = tid / 72;
    int cb = cg * 2;
    float2 sc2 = *(const float2*)&ssc[cb];
    float2 sh2 = *(const float2*)&ssh[cb];

    float s0 = 0.f, s1 = 0.f, q0 = 0.f, q1 = 0.f;
#pragma unroll 1
    for (int j = 0; j < 8; j++) {
        int r = rl * 8 + j;
        int n = cnt[r];
        float a0 = 0.f, a1 = 0.f;
        for (int i = 0; i < n; i++) {
            int p   = plist[r][i];
            int nbr = p >> 4;
            int k   = p & 15;
            float2 x = *(const float2*)&g_x1[(size_t)nbr * C_HID + cb];
            float2 w = *(const float2*)&sw2[k * C_HID + cb];
            float v0 = relu6f(fmaf(x.x, sc2.x, sh2.x));
            float v1 = relu6f(fmaf(x.y, sc2.y, sh2.y));
            a0 = fmaf(w.x, v0, a0);
            a1 = fmaf(w.y, v1, a1);
        }
        *(float2*)&g_x2[(size_t)(row0 + r) * C_HID + cb] = make_float2(a0, a1);
        s0 += a0; q0 += a0 * a0;
        s1 += a1; q1 += a1 * a1;
    }
    rs[rl][cb] = s0; rs[rl][cb + 1] = s1;
    rq[rl][cb] = q0; rq[rl][cb + 1] = q1;
    __syncthreads();
    if (tid < C_HID) {
        float s = rs[0][tid] + rs[1][tid] + rs[2][tid] + rs[3][tid];
        float q = rq[0][tid] + rq[1][tid] + rq[2][tid] + rq[3][tid];
        atomicAdd(&g_s2[tid], s);
        atomicAdd(&g_q2[tid], q);
    }
}

// ---- K5: y = relu6(bn2(x2)) @ w3 + BN3 stats (k-chunked smem) ----
#define R5 64
#define T5 192
#define KC 72
__global__ void __launch_bounds__(T5) k5_gemm3(const float* __restrict__ w3,
                                               const float* __restrict__ g2,
                                               const float* __restrict__ b2) {
    __shared__ __align__(16) float sxT[KC][R5 + 1];
    __shared__ __align__(16) float sw3[C_HID * C_OUT];
    __shared__ __align__(16) float rs[32][C_OUT], rq[32][C_OUT];
    __shared__ float ssc[C_HID], ssh[C_HID];

    int tid = threadIdx.x;
    int row0 = blockIdx.x * R5;

    for (int i = tid; i < C_HID * C_OUT; i += T5) sw3[i] = w3[i];
    if (tid < C_HID) {
        float m = g_s2[tid] * (1.0f / N_PTS);
        float v = g_q2[tid] * (1.0f / N_PTS) - m * m;
        float sc = g2[tid] * rsqrtf(v + EPS);
        ssc[tid] = sc;
        ssh[tid] = b2[tid] - m * sc;
    }

    int c4 = tid % 6, rg = tid / 6;
    int cb = c4 * 4;
    int r0 = rg * 2;
    float4 acc0 = make_float4(0.f, 0.f, 0.f, 0.f), acc1 = acc0;

    for (int kc = 0; kc < C_HID; kc += KC) {
        __syncthreads();
        for (int i = tid; i < KC * R5; i += T5) {
            int r = i / KC, k = i % KC;
            int rr = row0 + r;
            float v = 0.f;
            if (rr < N_PTS) {
                int ch = kc + k;
                float x = g_x2[(size_t)rr * C_HID + ch];
                v = relu6f(fmaf(x, ssc[ch], ssh[ch]));
            }
            sxT[k][r] = v;
        }
        __syncthreads();
#pragma unroll 8
        for (int k = 0; k < KC; k++) {
            float4 w = *(const float4*)&sw3[(kc + k) * C_OUT + cb];
            float x0 = sxT[k][r0];
            float x1 = sxT[k][r0 + 1];
            acc0.x = fmaf(w.x, x0, acc0.x); acc0.y = fmaf(w.y, x0, acc0.y);
            acc0.z = fmaf(w.z, x0, acc0.z); acc0.w = fmaf(w.w, x0, acc0.w);
            acc1.x = fmaf(w.x, x1, acc1.x); acc1.y = fmaf(w.y, x1, acc1.y);
            acc1.z = fmaf(w.z, x1, acc1.z); acc1.w = fmaf(w.w, x1, acc1.w);
        }
    }

    int rr0 = row0 + r0;
    if (rr0 < N_PTS)     *(float4*)&g_y[(size_t)rr0 * C_OUT + cb] = acc0;
    if (rr0 + 1 < N_PTS) *(float4*)&g_y[(size_t)(rr0 + 1) * C_OUT + cb] = acc1;

    float4 s4, q4;
    s4.x = acc0.x + acc1.x; s4.y = acc0.y + acc1.y;
    s4.z = acc0.z + acc1.z; s4.w = acc0.w + acc1.w;
    q4.x = acc0.x * acc0.x + acc1.x * acc1.x;
    q4.y = acc0.y * acc0.y + acc1.y * acc1.y;
    q4.z = acc0.z * acc0.z + acc1.z * acc1.z;
    q4.w = acc0.w * acc0.w + acc1.w * acc1.w;
    *(float4*)&rs[rg][cb] = s4;
    *(float4*)&rq[rg][cb] = q4;
    __syncthreads();
    if (tid < C_OUT) {
        float s = 0.f, q = 0.f;
#pragma unroll
        for (int g = 0; g < 32; g++) { s += rs[g][tid]; q += rq[g][tid]; }
        atomicAdd(&g_s3[tid], s);
        atomicAdd(&g_q3[tid], q);
    }
}

// ---- K7: out = bn3(y) + feats (float4); block0 zeroes stage-1 accumulators ----
__global__ void k7_out(const float* __restrict__ feats, float* __restrict__ out,
                       const float* __restrict__ g3, const float* __restrict__ b3) {
    __shared__ float ssc[C_OUT], ssh[C_OUT];
    int tid = threadIdx.x;
    if (blockIdx.x == 0 && tid < C_HID) { g_s1[tid] = 0.f; g_q1[tid] = 0.f; }
    if (tid < C_OUT) {
        float m = g_s3[tid] * (1.0f / N_PTS);
        float v = g_q3[tid] * (1.0f / N_PTS) - m * m;
        float sc = g3[tid] * rsqrtf(v + EPS);
        ssc[tid] = sc;
        ssh[tid] = b3[tid] - m * sc;
    }
    __syncthreads();

    int i = blockIdx.x * blockDim.x + tid;   // float4 index
    if (i < N_PTS * C_OUT / 4) {
        int cb = (i % 6) * 4;
        float4 y  = *(const float4*)&g_y[i * 4];
        float4 f  = *(const float4*)&feats[i * 4];
        float4 o;
        o.x = fmaf(y.x, ssc[cb + 0], ssh[cb + 0]) + f.x;
        o.y = fmaf(y.y, ssc[cb + 1], ssh[cb + 1]) + f.y;
        o.z = fmaf(y.z, ssc[cb + 2], ssh[cb + 2]) + f.z;
        o.w = fmaf(y.w, ssc[cb + 3], ssh[cb + 3]) + f.w;
        *(float4*)&out[i * 4] = o;
    }
}

extern "C" void kernel_launch(void* const* d_in, const int* in_sizes, int n_in,
                              void* d_out, int out_size) {
    const float* feats = (const float*)d_in[0];
    const float* w1    = (const float*)d_in[1];
    const float* g1    = (const float*)d_in[2];
    const float* b1    = (const float*)d_in[3];
    const float* w2    = (const float*)d_in[4];
    const float* g2    = (const float*)d_in[5];
    const float* b2    = (const float*)d_in[6];
    const float* w3    = (const float*)d_in[7];
    const float* g3    = (const float*)d_in[8];
    const float* b3    = (const float*)d_in[9];
    const int*   in_idx = (const int*)d_in[10];
    float* out = (float*)d_out;

    int nb1 = (N_PTS + R1 - 1) / R1;
    k1_gemm1<<<nb1, T1>>>(feats, w1);

    int nb3 = N_PTS / R3;   // exact
    k3_conv<<<nb3, T3>>>(w2, in_idx, g1, b1);

    int nb5 = (N_PTS + R5 - 1) / R5;
    k5_gemm3<<<nb5, T5>>>(w3, g2, b2);

    int total4 = N_PTS * C_OUT / 4;
    k7_out<<<(total4 + 255) / 256, 256>>>(feats, out, g3, b3);
}

// round 5
// speedup vs baseline: 1.0087x; 1.0087x over previous
#include <cuda_runtime.h>
#include <cuda_fp16.h>

#define N_PTS 100000
#define C_IN 24
#define C_HID 144
#define C_OUT 24
#define KS 9
#define EPS 1e-5f

// ---- scratch (device globals: allocation-free rule) ----
// g_x1h: fp16, one extra all-zero sentinel row at index N_PTS (never written -> stays 0).
__device__ __align__(16) __half g_x1h[(N_PTS + 1) * C_HID];
__device__ __align__(16) float  g_x2[N_PTS * C_HID];
__device__ __align__(16) float  g_y [N_PTS * C_OUT];

__device__ float g_s1[C_HID], g_q1[C_HID];
__device__ float g_s2[C_HID], g_q2[C_HID];
__device__ float g_s3[C_OUT], g_q3[C_OUT];

__device__ __forceinline__ float relu6f(float x) { return fminf(fmaxf(x, 0.f), 6.f); }

// ---- K1: x1 = feats @ w1 (fp16 out, fp32 stats); block0 zeroes stage-2 accums ----
#define R1 64
#define T1 288
__global__ void __launch_bounds__(T1) k1_gemm1(const float* __restrict__ feats,
                                               const float* __restrict__ w1) {
    __shared__ __align__(16) float sfT[C_IN][R1];
    __shared__ __align__(16) float sw1[C_IN * C_HID];
    __shared__ __align__(16) float rs[8][C_HID], rq[8][C_HID];

    int tid = threadIdx.x;
    int row0 = blockIdx.x * R1;

    if (blockIdx.x == 0 && tid < C_HID) { g_s2[tid] = 0.f; g_q2[tid] = 0.f; }

    for (int i = tid; i < C_IN * C_HID; i += T1) sw1[i] = w1[i];
    for (int i = tid; i < R1 * C_IN; i += T1) {
        int r = i / C_IN, k = i % C_IN;
        int rr = row0 + r;
        sfT[k][r] = (rr < N_PTS) ? feats[rr * C_IN + k] : 0.f;
    }
    __syncthreads();

    int c4 = tid % 36, rg = tid / 36;
    int cb = c4 * 4;
    float4 acc[8];
#pragma unroll
    for (int j = 0; j < 8; j++) acc[j] = make_float4(0.f, 0.f, 0.f, 0.f);

#pragma unroll
    for (int k = 0; k < C_IN; k++) {
        float4 w  = *(const float4*)&sw1[k * C_HID + cb];
        float4 xa = *(const float4*)&sfT[k][rg * 8];
        float4 xb = *(const float4*)&sfT[k][rg * 8 + 4];
        float xr[8] = {xa.x, xa.y, xa.z, xa.w, xb.x, xb.y, xb.z, xb.w};
#pragma unroll
        for (int j = 0; j < 8; j++) {
            acc[j].x = fmaf(w.x, xr[j], acc[j].x);
            acc[j].y = fmaf(w.y, xr[j], acc[j].y);
            acc[j].z = fmaf(w.z, xr[j], acc[j].z);
            acc[j].w = fmaf(w.w, xr[j], acc[j].w);
        }
    }

    float4 s4 = make_float4(0.f, 0.f, 0.f, 0.f), q4 = s4;
#pragma unroll
    for (int j = 0; j < 8; j++) {
        int rr = row0 + rg * 8 + j;
        if (rr < N_PTS) {
            __half2 h0 = __floats2half2_rn(acc[j].x, acc[j].y);
            __half2 h1 = __floats2half2_rn(acc[j].z, acc[j].w);
            uint2 pk;
            pk.x = *(unsigned int*)&h0;
            pk.y = *(unsigned int*)&h1;
            *(uint2*)&g_x1h[(size_t)rr * C_HID + cb] = pk;
        }
        s4.x += acc[j].x; s4.y += acc[j].y; s4.z += acc[j].z; s4.w += acc[j].w;
        q4.x += acc[j].x * acc[j].x; q4.y += acc[j].y * acc[j].y;
        q4.z += acc[j].z * acc[j].z; q4.w += acc[j].w * acc[j].w;
    }
    *(float4*)&rs[rg][cb] = s4;
    *(float4*)&rq[rg][cb] = q4;
    __syncthreads();
    if (tid < C_HID) {
        float s = 0.f, q = 0.f;
#pragma unroll
        for (int g = 0; g < 8; g++) { s += rs[g][tid]; q += rq[g][tid]; }
        atomicAdd(&g_s1[tid], s);
        atomicAdd(&g_q1[tid], q);
    }
}

// ---- K3: channelwise 3x3 sparse conv + BN2 stats ----
// Unconditional fp16 gathers (MLP=9), invalid neighbor killed by 0-mask multiply.
#define R3 32
#define T3 288   // 36 channel-groups (4ch, 8B) x 8 row-lanes (4 rows each)
__global__ void __launch_bounds__(T3) k3_conv(const float* __restrict__ w2,
                                              const int* __restrict__ in_idx,
                                              const float* __restrict__ g1,
                                              const float* __restrict__ b1) {
    __shared__ float ssc[C_HID], ssh[C_HID];
    __shared__ int snbr[R3][KS];
    __shared__ __align__(16) float rs[8][C_HID], rq[8][C_HID];

    int tid = threadIdx.x;
    int row0 = blockIdx.x * R3;      // N_PTS % R3 == 0

    if (blockIdx.x == 0 && tid < C_OUT) { g_s3[tid] = 0.f; g_q3[tid] = 0.f; }

    if (tid < C_HID) {
        float m = g_s1[tid] * (1.0f / N_PTS);
        float v = g_q1[tid] * (1.0f / N_PTS) - m * m;
        float sc = g1[tid] * rsqrtf(v + EPS);
        ssc[tid] = sc;
        ssh[tid] = b1[tid] - m * sc;
    }
    {   // T3 == R3*KS: one coalesced in_idx load per thread
        int k = tid / R3, r = tid % R3;
        snbr[r][k] = in_idx[k * N_PTS + row0 + r];
    }
    __syncthreads();

    int cg = tid % 36, rl = tid / 36;   // 4 channels per thread, rows rl*4..rl*4+3
    int cb = cg * 4;

    float4 wk[KS];
#pragma unroll
    for (int k = 0; k < KS; k++) wk[k] = *(const float4*)&w2[k * C_HID + cb];
    float4 sc4 = *(const float4*)&ssc[cb];
    float4 sh4 = *(const float4*)&ssh[cb];

    float4 s4 = make_float4(0.f, 0.f, 0.f, 0.f), q4 = s4;
#pragma unroll
    for (int j = 0; j < 4; j++) {
        int r = rl * 4 + j;
        int nb[KS];
        uint2 h[KS];
#pragma unroll
        for (int k = 0; k < KS; k++) nb[k] = snbr[r][k];
#pragma unroll
        for (int k = 0; k < KS; k++)   // unconditional: sentinel row N_PTS is all zeros
            h[k] = *(const uint2*)&g_x1h[(size_t)nb[k] * C_HID + cb];

        float4 acc = make_float4(0.f, 0.f, 0.f, 0.f);
#pragma unroll
        for (int k = 0; k < KS; k++) {
            float m = (nb[k] < N_PTS) ? 1.f : 0.f;
            __half2 h0 = *(__half2*)&h[k].x;
            __half2 h1 = *(__half2*)&h[k].y;
            float2 lo = __half22float2(h0);
            float2 hi = __half22float2(h1);
            float v0 = relu6f(fmaf(lo.x, sc4.x, sh4.x)) * m;
            float v1 = relu6f(fmaf(lo.y, sc4.y, sh4.y)) * m;
            float v2 = relu6f(fmaf(hi.x, sc4.z, sh4.z)) * m;
            float v3 = relu6f(fmaf(hi.y, sc4.w, sh4.w)) * m;
            acc.x = fmaf(wk[k].x, v0, acc.x);
            acc.y = fmaf(wk[k].y, v1, acc.y);
            acc.z = fmaf(wk[k].z, v2, acc.z);
            acc.w = fmaf(wk[k].w, v3, acc.w);
        }
        *(float4*)&g_x2[(size_t)(row0 + r) * C_HID + cb] = acc;
        s4.x += acc.x; s4.y += acc.y; s4.z += acc.z; s4.w += acc.w;
        q4.x += acc.x * acc.x; q4.y += acc.y * acc.y;
        q4.z += acc.z * acc.z; q4.w += acc.w * acc.w;
    }
    *(float4*)&rs[rl][cb] = s4;
    *(float4*)&rq[rl][cb] = q4;
    __syncthreads();
    if (tid < C_HID) {
        float s = 0.f, q = 0.f;
#pragma unroll
        for (int g = 0; g < 8; g++) { s += rs[g][tid]; q += rq[g][tid]; }
        atomicAdd(&g_s2[tid], s);
        atomicAdd(&g_q2[tid], q);
    }
}

// ---- K5: y = relu6(bn2(x2)) @ w3 + BN3 stats; 4 rows x 4 cols per thread ----
#define R5 128
#define T5 192
#define KC5 36
__global__ void __launch_bounds__(T5) k5_gemm3(const float* __restrict__ w3,
                                               const float* __restrict__ g2,
                                               const float* __restrict__ b2) {
    __shared__ __align__(16) float sxT[KC5][R5 + 4];
    __shared__ __align__(16) float sw3[C_HID * C_OUT];
    __shared__ __align__(16) float rs[32][C_OUT], rq[32][C_OUT];
    __shared__ float ssc[C_HID], ssh[C_HID];

    int tid = threadIdx.x;
    int row0 = blockIdx.x * R5;

    for (int i = tid; i < C_HID * C_OUT; i += T5) sw3[i] = w3[i];
    if (tid < C_HID) {
        float m = g_s2[tid] * (1.0f / N_PTS);
        float v = g_q2[tid] * (1.0f / N_PTS) - m * m;
        float sc = g2[tid] * rsqrtf(v + EPS);
        ssc[tid] = sc;
        ssh[tid] = b2[tid] - m * sc;
    }

    int c4 = tid % 6, rg = tid / 6;    // cols c4*4..+3, rows rg*4..+3
    int cb = c4 * 4;
    int r0 = rg * 4;
    float4 acc[4];
#pragma unroll
    for (int j = 0; j < 4; j++) acc[j] = make_float4(0.f, 0.f, 0.f, 0.f);

    for (int kc = 0; kc < C_HID; kc += KC5) {
        __syncthreads();
        for (int i = tid; i < KC5 * R5; i += T5) {
            int r = i / KC5, k = i % KC5;
            int rr = row0 + r;
            float v = 0.f;
            if (rr < N_PTS) {
                int ch = kc + k;
                float x = g_x2[(size_t)rr * C_HID + ch];
                v = relu6f(fmaf(x, ssc[ch], ssh[ch]));
            }
            sxT[k][r] = v;
        }
        __syncthreads();
#pragma unroll
        for (int k = 0; k < KC5; k++) {
            float4 w = *(const float4*)&sw3[(kc + k) * C_OUT + cb];
            float4 x = *(const float4*)&sxT[k][r0];
            float xr[4] = {x.x, x.y, x.z, x.w};
#pragma unroll
            for (int j = 0; j < 4; j++) {
                acc[j].x = fmaf(w.x, xr[j], acc[j].x);
                acc[j].y = fmaf(w.y, xr[j], acc[j].y);
                acc[j].z = fmaf(w.z, xr[j], acc[j].z);
                acc[j].w = fmaf(w.w, xr[j], acc[j].w);
            }
        }
    }

    float4 s4 = make_float4(0.f, 0.f, 0.f, 0.f), q4 = s4;
#pragma unroll
    for (int j = 0; j < 4; j++) {
        int rr = row0 + r0 + j;
        if (rr < N_PTS) *(float4*)&g_y[(size_t)rr * C_OUT + cb] = acc[j];
        s4.x += acc[j].x; s4.y += acc[j].y; s4.z += acc[j].z; s4.w += acc[j].w;
        q4.x += acc[j].x * acc[j].x; q4.y += acc[j].y * acc[j].y;
        q4.z += acc[j].z * acc[j].z; q4.w += acc[j].w * acc[j].w;
    }
    *(float4*)&rs[rg][cb] = s4;
    *(float4*)&rq[rg][cb] = q4;
    __syncthreads();
    if (tid < C_OUT) {
        float s = 0.f, q = 0.f;
#pragma unroll
        for (int g = 0; g < 32; g++) { s += rs[g][tid]; q += rq[g][tid]; }
        atomicAdd(&g_s3[tid], s);
        atomicAdd(&g_q3[tid], q);
    }
}

// ---- K7: out = bn3(y) + feats (float4); block0 zeroes stage-1 accumulators ----
__global__ void k7_out(const float* __restrict__ feats, float* __restrict__ out,
                       const float* __restrict__ g3, const float* __restrict__ b3) {
    __shared__ float ssc[C_OUT], ssh[C_OUT];
    int tid = threadIdx.x;
    if (blockIdx.x == 0 && tid < C_HID) { g_s1[tid] = 0.f; g_q1[tid] = 0.f; }
    if (tid < C_OUT) {
        float m = g_s3[tid] * (1.0f / N_PTS);
        float v = g_q3[tid] * (1.0f / N_PTS) - m * m;
        float sc = g3[tid] * rsqrtf(v + EPS);
        ssc[tid] = sc;
        ssh[tid] = b3[tid] - m * sc;
    }
    __syncthreads();

    int i = blockIdx.x * blockDim.x + tid;   // float4 index
    if (i < N_PTS * C_OUT / 4) {
        int cb = (i % 6) * 4;
        float4 y  = *(const float4*)&g_y[i * 4];
        float4 f  = *(const float4*)&feats[i * 4];
        float4 o;
        o.x = fmaf(y.x, ssc[cb + 0], ssh[cb + 0]) + f.x;
        o.y = fmaf(y.y, ssc[cb + 1], ssh[cb + 1]) + f.y;
        o.z = fmaf(y.z, ssc[cb + 2], ssh[cb + 2]) + f.z;
        o.w = fmaf(y.w, ssc[cb + 3], ssh[cb + 3]) + f.w;
        *(float4*)&out[i * 4] = o;
    }
}

extern "C" void kernel_launch(void* const* d_in, const int* in_sizes, int n_in,
                              void* d_out, int out_size) {
    const float* feats = (const float*)d_in[0];
    const float* w1    = (const float*)d_in[1];
    const float* g1    = (const float*)d_in[2];
    const float* b1    = (const float*)d_in[3];
    const float* w2    = (const float*)d_in[4];
    const float* g2    = (const float*)d_in[5];
    const float* b2    = (const float*)d_in[6];
    const float* w3    = (const float*)d_in[7];
    const float* g3    = (const float*)d_in[8];
    const float* b3    = (const float*)d_in[9];
    const int*   in_idx = (const int*)d_in[10];
    float* out = (float*)d_out;

    int nb1 = (N_PTS + R1 - 1) / R1;
    k1_gemm1<<<nb1, T1>>>(feats, w1);

    int nb3 = N_PTS / R3;   // exact
    k3_conv<<<nb3, T3>>>(w2, in_idx, g1, b1);

    int nb5 = (N_PTS + R5 - 1) / R5;
    k5_gemm3<<<nb5, T5>>>(w3, g2, b2);

    int total4 = N_PTS * C_OUT / 4;
    k7_out<<<(total4 + 255) / 256, 256>>>(feats, out, g3, b3);
}

// round 6
// speedup vs baseline: 1.2332x; 1.2226x over previous
#include <cuda_runtime.h>
#include <cuda_fp16.h>

#define N_PTS 100000
#define C_IN 24
#define C_HID 144
#define C_OUT 24
#define KS 9
#define EPS 1e-5f

// ---- scratch (device globals: allocation-free rule) ----
// g_x1h: fp16, one extra all-zero sentinel row at index N_PTS (never written -> stays 0).
__device__ __align__(16) __half g_x1h[(N_PTS + 1) * C_HID];
__device__ __align__(16) __half g_x2h[N_PTS * C_HID];
__device__ __align__(16) float  g_y [N_PTS * C_OUT];

__device__ float g_s1[C_HID], g_q1[C_HID];
__device__ float g_s2[C_HID], g_q2[C_HID];
__device__ float g_s3[C_OUT], g_q3[C_OUT];

__device__ __forceinline__ float relu6f(float x) { return fminf(fmaxf(x, 0.f), 6.f); }

// ---- K1: x1 = feats @ w1 (fp16 out, fp32 stats); block0 zeroes stage-2 accums ----
#define R1 64
#define T1 288
__global__ void __launch_bounds__(T1) k1_gemm1(const float* __restrict__ feats,
                                               const float* __restrict__ w1) {
    __shared__ __align__(16) float sfT[C_IN][R1];
    __shared__ __align__(16) float sw1[C_IN * C_HID];
    __shared__ __align__(16) float rs[8][C_HID], rq[8][C_HID];

    int tid = threadIdx.x;
    int row0 = blockIdx.x * R1;

    if (blockIdx.x == 0 && tid < C_HID) { g_s2[tid] = 0.f; g_q2[tid] = 0.f; }

    for (int i = tid; i < C_IN * C_HID; i += T1) sw1[i] = w1[i];
    for (int i = tid; i < R1 * C_IN; i += T1) {
        int r = i / C_IN, k = i % C_IN;
        int rr = row0 + r;
        sfT[k][r] = (rr < N_PTS) ? feats[rr * C_IN + k] : 0.f;
    }
    __syncthreads();

    int c4 = tid % 36, rg = tid / 36;
    int cb = c4 * 4;
    float4 acc[8];
#pragma unroll
    for (int j = 0; j < 8; j++) acc[j] = make_float4(0.f, 0.f, 0.f, 0.f);

#pragma unroll
    for (int k = 0; k < C_IN; k++) {
        float4 w  = *(const float4*)&sw1[k * C_HID + cb];
        float4 xa = *(const float4*)&sfT[k][rg * 8];
        float4 xb = *(const float4*)&sfT[k][rg * 8 + 4];
        float xr[8] = {xa.x, xa.y, xa.z, xa.w, xb.x, xb.y, xb.z, xb.w};
#pragma unroll
        for (int j = 0; j < 8; j++) {
            acc[j].x = fmaf(w.x, xr[j], acc[j].x);
            acc[j].y = fmaf(w.y, xr[j], acc[j].y);
            acc[j].z = fmaf(w.z, xr[j], acc[j].z);
            acc[j].w = fmaf(w.w, xr[j], acc[j].w);
        }
    }

    float4 s4 = make_float4(0.f, 0.f, 0.f, 0.f), q4 = s4;
#pragma unroll
    for (int j = 0; j < 8; j++) {
        int rr = row0 + rg * 8 + j;
        if (rr < N_PTS) {
            __half2 h0 = __floats2half2_rn(acc[j].x, acc[j].y);
            __half2 h1 = __floats2half2_rn(acc[j].z, acc[j].w);
            uint2 pk;
            pk.x = *(unsigned int*)&h0;
            pk.y = *(unsigned int*)&h1;
            *(uint2*)&g_x1h[(size_t)rr * C_HID + cb] = pk;
        }
        s4.x += acc[j].x; s4.y += acc[j].y; s4.z += acc[j].z; s4.w += acc[j].w;
        q4.x += acc[j].x * acc[j].x; q4.y += acc[j].y * acc[j].y;
        q4.z += acc[j].z * acc[j].z; q4.w += acc[j].w * acc[j].w;
    }
    *(float4*)&rs[rg][cb] = s4;
    *(float4*)&rq[rg][cb] = q4;
    __syncthreads();
    if (tid < C_HID) {
        float s = 0.f, q = 0.f;
#pragma unroll
        for (int g = 0; g < 8; g++) { s += rs[g][tid]; q += rq[g][tid]; }
        atomicAdd(&g_s1[tid], s);
        atomicAdd(&g_q1[tid], q);
    }
}

// ---- K3: channelwise 3x3 sparse conv + BN2 stats ----
// 2 channels/thread (half2), unconditional 4B gathers, mask-multiply for invalids.
#define R3 64
#define T3 288   // 72 channel-pairs x 4 row-lanes; each thread does 16 rows
__global__ void __launch_bounds__(T3) k3_conv(const float* __restrict__ w2,
                                              const int* __restrict__ in_idx,
                                              const float* __restrict__ g1,
                                              const float* __restrict__ b1) {
    __shared__ float ssc[C_HID], ssh[C_HID];
    __shared__ int snbr[R3][KS];
    __shared__ __align__(8) float rs[4][C_HID], rq[4][C_HID];

    int tid = threadIdx.x;
    int row0 = blockIdx.x * R3;      // N_PTS % R3 != 0 handled by row guard on stores

    if (blockIdx.x == 0 && tid < C_OUT) { g_s3[tid] = 0.f; g_q3[tid] = 0.f; }

    if (tid < C_HID) {
        float m = g_s1[tid] * (1.0f / N_PTS);
        float v = g_q1[tid] * (1.0f / N_PTS) - m * m;
        float sc = g1[tid] * rsqrtf(v + EPS);
        ssc[tid] = sc;
        ssh[tid] = b1[tid] - m * sc;
    }
    // stage neighbor indices: KS*R3 = 576 = 2*T3
#pragma unroll
    for (int t = 0; t < 2; t++) {
        int i = tid + t * T3;
        int k = i / R3, r = i % R3;
        int rr = row0 + r;
        snbr[r][k] = (rr < N_PTS) ? in_idx[k * N_PTS + rr] : N_PTS;
    }
    __syncthreads();

    int cg = tid % 72, rl = tid / 72;   // 2 channels, rows rl*16..rl*16+15
    int cb = cg * 2;

    float2 wk[KS];
#pragma unroll
    for (int k = 0; k < KS; k++) wk[k] = *(const float2*)&w2[k * C_HID + cb];
    float2 sc2 = *(const float2*)&ssc[cb];
    float2 sh2 = *(const float2*)&ssh[cb];

    float s0 = 0.f, s1 = 0.f, q0 = 0.f, q1 = 0.f;
#pragma unroll 2
    for (int j = 0; j < 16; j++) {
        int r = rl * 16 + j;
        int nb[KS];
        unsigned int h[KS];
#pragma unroll
        for (int k = 0; k < KS; k++) nb[k] = snbr[r][k];
#pragma unroll
        for (int k = 0; k < KS; k++)   // sentinel row N_PTS is all zeros -> safe
            h[k] = *(const unsigned int*)&g_x1h[nb[k] * C_HID + cb];

        float a0 = 0.f, a1 = 0.f;
#pragma unroll
        for (int k = 0; k < KS; k++) {
            float m = (nb[k] < N_PTS) ? 1.f : 0.f;
            float2 x = __half22float2(*(__half2*)&h[k]);
            float v0 = relu6f(fmaf(x.x, sc2.x, sh2.x)) * m;
            float v1 = relu6f(fmaf(x.y, sc2.y, sh2.y)) * m;
            a0 = fmaf(wk[k].x, v0, a0);
            a1 = fmaf(wk[k].y, v1, a1);
        }
        int rr = row0 + r;
        if (rr < N_PTS) {
            __half2 hh = __floats2half2_rn(a0, a1);
            *(unsigned int*)&g_x2h[(size_t)rr * C_HID + cb] = *(unsigned int*)&hh;
            s0 += a0; q0 += a0 * a0;
            s1 += a1; q1 += a1 * a1;
        }
    }
    rs[rl][cb] = s0; rs[rl][cb + 1] = s1;
    rq[rl][cb] = q0; rq[rl][cb + 1] = q1;
    __syncthreads();
    if (tid < C_HID) {
        float s = rs[0][tid] + rs[1][tid] + rs[2][tid] + rs[3][tid];
        float q = rq[0][tid] + rq[1][tid] + rq[2][tid] + rq[3][tid];
        atomicAdd(&g_s2[tid], s);
        atomicAdd(&g_q2[tid], q);
    }
}

// ---- K5: y = relu6(bn2(x2)) @ w3 + BN3 stats; 4 rows x 4 cols per thread ----
#define R5 128
#define T5 192
#define KC5 36
__global__ void __launch_bounds__(T5) k5_gemm3(const float* __restrict__ w3,
                                               const float* __restrict__ g2,
                                               const float* __restrict__ b2) {
    __shared__ __align__(16) float sxT[KC5][R5 + 4];
    __shared__ __align__(16) float sw3[C_HID * C_OUT];
    __shared__ __align__(16) float rs[32][C_OUT], rq[32][C_OUT];
    __shared__ float ssc[C_HID], ssh[C_HID];

    int tid = threadIdx.x;
    int row0 = blockIdx.x * R5;

    for (int i = tid; i < C_HID * C_OUT; i += T5) sw3[i] = w3[i];
    if (tid < C_HID) {
        float m = g_s2[tid] * (1.0f / N_PTS);
        float v = g_q2[tid] * (1.0f / N_PTS) - m * m;
        float sc = g2[tid] * rsqrtf(v + EPS);
        ssc[tid] = sc;
        ssh[tid] = b2[tid] - m * sc;
    }

    int c4 = tid % 6, rg = tid / 6;    // cols c4*4..+3, rows rg*4..+3
    int cb = c4 * 4;
    int r0 = rg * 4;
    float4 acc[4];
#pragma unroll
    for (int j = 0; j < 4; j++) acc[j] = make_float4(0.f, 0.f, 0.f, 0.f);

    for (int kc = 0; kc < C_HID; kc += KC5) {
        __syncthreads();
        // stage: 36 channels x 128 rows from fp16, uint2 = 4 halfs per load
        for (int i = tid; i < (KC5 / 4) * R5; i += T5) {
            int r = i / 9, kq = i % 9;           // 9 uint2 per row chunk
            int rr = row0 + r;
            float x0 = 0.f, x1 = 0.f, x2 = 0.f, x3 = 0.f;
            int ch = kc + kq * 4;
            if (rr < N_PTS) {
                uint2 u = *(const uint2*)&g_x2h[(size_t)rr * C_HID + ch];
                float2 lo = __half22float2(*(__half2*)&u.x);
                float2 hi = __half22float2(*(__half2*)&u.y);
                x0 = relu6f(fmaf(lo.x, ssc[ch + 0], ssh[ch + 0]));
                x1 = relu6f(fmaf(lo.y, ssc[ch + 1], ssh[ch + 1]));
                x2 = relu6f(fmaf(hi.x, ssc[ch + 2], ssh[ch + 2]));
                x3 = relu6f(fmaf(hi.y, ssc[ch + 3], ssh[ch + 3]));
            }
            int kl = kq * 4;
            sxT[kl + 0][r] = x0;
            sxT[kl + 1][r] = x1;
            sxT[kl + 2][r] = x2;
            sxT[kl + 3][r] = x3;
        }
        __syncthreads();
#pragma unroll
        for (int k = 0; k < KC5; k++) {
            float4 w = *(const float4*)&sw3[(kc + k) * C_OUT + cb];
            float4 x = *(const float4*)&sxT[k][r0];
            float xr[4] = {x.x, x.y, x.z, x.w};
#pragma unroll
            for (int j = 0; j < 4; j++) {
                acc[j].x = fmaf(w.x, xr[j], acc[j].x);
                acc[j].y = fmaf(w.y, xr[j], acc[j].y);
                acc[j].z = fmaf(w.z, xr[j], acc[j].z);
                acc[j].w = fmaf(w.w, xr[j], acc[j].w);
            }
        }
    }

    float4 s4 = make_float4(0.f, 0.f, 0.f, 0.f), q4 = s4;
#pragma unroll
    for (int j = 0; j < 4; j++) {
        int rr = row0 + r0 + j;
        if (rr < N_PTS) {
            *(float4*)&g_y[(size_t)rr * C_OUT + cb] = acc[j];
            s4.x += acc[j].x; s4.y += acc[j].y; s4.z += acc[j].z; s4.w += acc[j].w;
            q4.x += acc[j].x * acc[j].x; q4.y += acc[j].y * acc[j].y;
            q4.z += acc[j].z * acc[j].z; q4.w += acc[j].w * acc[j].w;
        }
    }
    *(float4*)&rs[rg][cb] = s4;
    *(float4*)&rq[rg][cb] = q4;
    __syncthreads();
    if (tid < C_OUT) {
        float s = 0.f, q = 0.f;
#pragma unroll
        for (int g = 0; g < 32; g++) { s += rs[g][tid]; q += rq[g][tid]; }
        atomicAdd(&g_s3[tid], s);
        atomicAdd(&g_q3[tid], q);
    }
}

// ---- K7: out = bn3(y) + feats (float4); block0 zeroes stage-1 accumulators ----
__global__ void k7_out(const float* __restrict__ feats, float* __restrict__ out,
                       const float* __restrict__ g3, const float* __restrict__ b3) {
    __shared__ float ssc[C_OUT], ssh[C_OUT];
    int tid = threadIdx.x;
    if (blockIdx.x == 0 && tid < C_HID) { g_s1[tid] = 0.f; g_q1[tid] = 0.f; }
    if (tid < C_OUT) {
        float m = g_s3[tid] * (1.0f / N_PTS);
        float v = g_q3[tid] * (1.0f / N_PTS) - m * m;
        float sc = g3[tid] * rsqrtf(v + EPS);
        ssc[tid] = sc;
        ssh[tid] = b3[tid] - m * sc;
    }
    __syncthreads();

    int i = blockIdx.x * blockDim.x + tid;   // float4 index
    if (i < N_PTS * C_OUT / 4) {
        int cb = (i % 6) * 4;
        float4 y  = *(const float4*)&g_y[i * 4];
        float4 f  = *(const float4*)&feats[i * 4];
        float4 o;
        o.x = fmaf(y.x, ssc[cb + 0], ssh[cb + 0]) + f.x;
        o.y = fmaf(y.y, ssc[cb + 1], ssh[cb + 1]) + f.y;
        o.z = fmaf(y.z, ssc[cb + 2], ssh[cb + 2]) + f.z;
        o.w = fmaf(y.w, ssc[cb + 3], ssh[cb + 3]) + f.w;
        *(float4*)&out[i * 4] = o;
    }
}

extern "C" void kernel_launch(void* const* d_in, const int* in_sizes, int n_in,
                              void* d_out, int out_size) {
    const float* feats = (const float*)d_in[0];
    const float* w1    = (const float*)d_in[1];
    const float* g1    = (const float*)d_in[2];
    const float* b1    = (const float*)d_in[3];
    const float* w2    = (const float*)d_in[4];
    const float* g2    = (const float*)d_in[5];
    const float* b2    = (const float*)d_in[6];
    const float* w3    = (const float*)d_in[7];
    const float* g3    = (const float*)d_in[8];
    const float* b3    = (const float*)d_in[9];
    const int*   in_idx = (const int*)d_in[10];
    float* out = (float*)d_out;

    int nb1 = (N_PTS + R1 - 1) / R1;
    k1_gemm1<<<nb1, T1>>>(feats, w1);

    int nb3 = (N_PTS + R3 - 1) / R3;
    k3_conv<<<nb3, T3>>>(w2, in_idx, g1, b1);

    int nb5 = (N_PTS + R5 - 1) / R5;
    k5_gemm3<<<nb5, T5>>>(w3, g2, b2);

    int total4 = N_PTS * C_OUT / 4;
    k7_out<<<(total4 + 255) / 256, 256>>>(feats, out, g3, b3);
}

// round 7
// speedup vs baseline: 1.3088x; 1.0613x over previous
#include <cuda_runtime.h>
#include <cuda_fp16.h>

#define N_PTS 100000
#define C_IN 24
#define C_HID 144
#define C_OUT 24
#define KS 9
#define EPS 1e-5f

// ---- scratch (device globals: allocation-free rule) ----
// g_x1h: fp16; extra all-zero sentinel row at index N_PTS (never written -> stays 0).
// After k2_act it holds relu6(bn1(x1)) so invalid gathers contribute exactly 0.
__device__ __align__(16) __half g_x1h[(N_PTS + 1) * C_HID];
__device__ __align__(16) __half g_x2h[N_PTS * C_HID];
__device__ __align__(16) float  g_y [N_PTS * C_OUT];

__device__ float g_s1[C_HID], g_q1[C_HID];
__device__ float g_s2[C_HID], g_q2[C_HID];
__device__ float g_s3[C_OUT], g_q3[C_OUT];

__device__ __forceinline__ float relu6f(float x) { return fminf(fmaxf(x, 0.f), 6.f); }

// ---- K1: x1 = feats @ w1 (fp16 out, fp32 stats); block0 zeroes stage-2 accums ----
#define R1 64
#define T1 288
__global__ void __launch_bounds__(T1) k1_gemm1(const float* __restrict__ feats,
                                               const float* __restrict__ w1) {
    __shared__ __align__(16) float sfT[C_IN][R1];
    __shared__ __align__(16) float sw1[C_IN * C_HID];
    __shared__ __align__(16) float rs[8][C_HID], rq[8][C_HID];

    int tid = threadIdx.x;
    int row0 = blockIdx.x * R1;

    if (blockIdx.x == 0 && tid < C_HID) { g_s2[tid] = 0.f; g_q2[tid] = 0.f; }

    for (int i = tid; i < C_IN * C_HID; i += T1) sw1[i] = w1[i];
    for (int i = tid; i < R1 * C_IN; i += T1) {
        int r = i / C_IN, k = i % C_IN;
        int rr = row0 + r;
        sfT[k][r] = (rr < N_PTS) ? feats[rr * C_IN + k] : 0.f;
    }
    __syncthreads();

    int c4 = tid % 36, rg = tid / 36;
    int cb = c4 * 4;
    float4 acc[8];
#pragma unroll
    for (int j = 0; j < 8; j++) acc[j] = make_float4(0.f, 0.f, 0.f, 0.f);

#pragma unroll
    for (int k = 0; k < C_IN; k++) {
        float4 w  = *(const float4*)&sw1[k * C_HID + cb];
        float4 xa = *(const float4*)&sfT[k][rg * 8];
        float4 xb = *(const float4*)&sfT[k][rg * 8 + 4];
        float xr[8] = {xa.x, xa.y, xa.z, xa.w, xb.x, xb.y, xb.z, xb.w};
#pragma unroll
        for (int j = 0; j < 8; j++) {
            acc[j].x = fmaf(w.x, xr[j], acc[j].x);
            acc[j].y = fmaf(w.y, xr[j], acc[j].y);
            acc[j].z = fmaf(w.z, xr[j], acc[j].z);
            acc[j].w = fmaf(w.w, xr[j], acc[j].w);
        }
    }

    float4 s4 = make_float4(0.f, 0.f, 0.f, 0.f), q4 = s4;
#pragma unroll
    for (int j = 0; j < 8; j++) {
        int rr = row0 + rg * 8 + j;
        if (rr < N_PTS) {
            __half2 h0 = __floats2half2_rn(acc[j].x, acc[j].y);
            __half2 h1 = __floats2half2_rn(acc[j].z, acc[j].w);
            uint2 pk;
            pk.x = *(unsigned int*)&h0;
            pk.y = *(unsigned int*)&h1;
            *(uint2*)&g_x1h[(size_t)rr * C_HID + cb] = pk;
        }
        s4.x += acc[j].x; s4.y += acc[j].y; s4.z += acc[j].z; s4.w += acc[j].w;
        q4.x += acc[j].x * acc[j].x; q4.y += acc[j].y * acc[j].y;
        q4.z += acc[j].z * acc[j].z; q4.w += acc[j].w * acc[j].w;
    }
    *(float4*)&rs[rg][cb] = s4;
    *(float4*)&rq[rg][cb] = q4;
    __syncthreads();
    if (tid < C_HID) {
        float s = 0.f, q = 0.f;
#pragma unroll
        for (int g = 0; g < 8; g++) { s += rs[g][tid]; q += rq[g][tid]; }
        atomicAdd(&g_s1[tid], s);
        atomicAdd(&g_q1[tid], q);
    }
}

// ---- K2: in-place activation x1 <- relu6(bn1(x1)), fp16 ----
#define T2 256
__global__ void __launch_bounds__(T2) k2_act(const float* __restrict__ g1,
                                             const float* __restrict__ b1) {
    __shared__ float ssc[C_HID], ssh[C_HID];
    int tid = threadIdx.x;
    if (tid < C_HID) {
        float m = g_s1[tid] * (1.0f / N_PTS);
        float v = g_q1[tid] * (1.0f / N_PTS) - m * m;
        float sc = g1[tid] * rsqrtf(v + EPS);
        ssc[tid] = sc;
        ssh[tid] = b1[tid] - m * sc;
    }
    __syncthreads();

    size_t i = (size_t)blockIdx.x * T2 + tid;        // uint2 = 4 halfs
    const size_t total = (size_t)N_PTS * C_HID / 4;
    if (i < total) {
        int ch = (int)((i * 4) % C_HID);
        uint2 u = *(const uint2*)&g_x1h[i * 4];
        float2 lo = __half22float2(*(__half2*)&u.x);
        float2 hi = __half22float2(*(__half2*)&u.y);
        float v0 = relu6f(fmaf(lo.x, ssc[ch + 0], ssh[ch + 0]));
        float v1 = relu6f(fmaf(lo.y, ssc[ch + 1], ssh[ch + 1]));
        float v2 = relu6f(fmaf(hi.x, ssc[ch + 2], ssh[ch + 2]));
        float v3 = relu6f(fmaf(hi.y, ssc[ch + 3], ssh[ch + 3]));
        __half2 h0 = __floats2half2_rn(v0, v1);
        __half2 h1 = __floats2half2_rn(v2, v3);
        uint2 pk;
        pk.x = *(unsigned int*)&h0;
        pk.y = *(unsigned int*)&h1;
        *(uint2*)&g_x1h[i * 4] = pk;
    }
}

// ---- K3: pure weighted gather conv + BN2 stats ----
// x1 is pre-activated; sentinel row zero -> no masking, no bn in inner loop.
#define R3 64
#define T3 288   // 72 channel-pairs x 4 row-lanes; each thread does 16 rows
__global__ void __launch_bounds__(T3) k3_conv(const float* __restrict__ w2,
                                              const int* __restrict__ in_idx) {
    __shared__ int snbr[R3][KS];
    __shared__ __align__(8) float rs[4][C_HID], rq[4][C_HID];

    int tid = threadIdx.x;
    int row0 = blockIdx.x * R3;

    if (blockIdx.x == 0 && tid < C_OUT) { g_s3[tid] = 0.f; g_q3[tid] = 0.f; }

    // stage neighbor indices: KS*R3 = 576 = 2*T3
#pragma unroll
    for (int t = 0; t < 2; t++) {
        int i = tid + t * T3;
        int k = i / R3, r = i % R3;
        int rr = row0 + r;
        snbr[r][k] = (rr < N_PTS) ? in_idx[k * N_PTS + rr] : N_PTS;
    }
    __syncthreads();

    int cg = tid % 72, rl = tid / 72;   // 2 channels, rows rl*16..rl*16+15
    int cb = cg * 2;

    float2 wk[KS];
#pragma unroll
    for (int k = 0; k < KS; k++) wk[k] = *(const float2*)&w2[k * C_HID + cb];

    float s0 = 0.f, s1 = 0.f, q0 = 0.f, q1 = 0.f;
#pragma unroll 2
    for (int j = 0; j < 16; j++) {
        int r = rl * 16 + j;
        unsigned int h[KS];
#pragma unroll
        for (int k = 0; k < KS; k++)   // sentinel row N_PTS is all zeros -> safe
            h[k] = *(const unsigned int*)&g_x1h[snbr[r][k] * C_HID + cb];

        float a0 = 0.f, a1 = 0.f;
#pragma unroll
        for (int k = 0; k < KS; k++) {
            float2 x = __half22float2(*(__half2*)&h[k]);
            a0 = fmaf(wk[k].x, x.x, a0);
            a1 = fmaf(wk[k].y, x.y, a1);
        }
        int rr = row0 + r;
        if (rr < N_PTS) {
            __half2 hh = __floats2half2_rn(a0, a1);
            *(unsigned int*)&g_x2h[(size_t)rr * C_HID + cb] = *(unsigned int*)&hh;
            s0 += a0; q0 += a0 * a0;
            s1 += a1; q1 += a1 * a1;
        }
    }
    rs[rl][cb] = s0; rs[rl][cb + 1] = s1;
    rq[rl][cb] = q0; rq[rl][cb + 1] = q1;
    __syncthreads();
    if (tid < C_HID) {
        float s = rs[0][tid] + rs[1][tid] + rs[2][tid] + rs[3][tid];
        float q = rq[0][tid] + rq[1][tid] + rq[2][tid] + rq[3][tid];
        atomicAdd(&g_s2[tid], s);
        atomicAdd(&g_q2[tid], q);
    }
}

// ---- K5: y = relu6(bn2(x2)) @ w3 + BN3 stats; 4 rows x 4 cols per thread ----
#define R5 128
#define T5 192
#define KC5 36
__global__ void __launch_bounds__(T5) k5_gemm3(const float* __restrict__ w3,
                                               const float* __restrict__ g2,
                                               const float* __restrict__ b2) {
    __shared__ __align__(16) float sxT[KC5][R5 + 4];
    __shared__ __align__(16) float sw3[C_HID * C_OUT];
    __shared__ __align__(16) float rs[32][C_OUT], rq[32][C_OUT];
    __shared__ float ssc[C_HID], ssh[C_HID];

    int tid = threadIdx.x;
    int row0 = blockIdx.x * R5;

    for (int i = tid; i < C_HID * C_OUT; i += T5) sw3[i] = w3[i];
    if (tid < C_HID) {
        float m = g_s2[tid] * (1.0f / N_PTS);
        float v = g_q2[tid] * (1.0f / N_PTS) - m * m;
        float sc = g2[tid] * rsqrtf(v + EPS);
        ssc[tid] = sc;
        ssh[tid] = b2[tid] - m * sc;
    }

    int c4 = tid % 6, rg = tid / 6;    // cols c4*4..+3, rows rg*4..+3
    int cb = c4 * 4;
    int r0 = rg * 4;
    float4 acc[4];
#pragma unroll
    for (int j = 0; j < 4; j++) acc[j] = make_float4(0.f, 0.f, 0.f, 0.f);

    for (int kc = 0; kc < C_HID; kc += KC5) {
        __syncthreads();
        for (int i = tid; i < (KC5 / 4) * R5; i += T5) {
            int r = i / 9, kq = i % 9;           // 9 uint2 per row chunk
            int rr = row0 + r;
            float x0 = 0.f, x1 = 0.f, x2 = 0.f, x3 = 0.f;
            int ch = kc + kq * 4;
            if (rr < N_PTS) {
                uint2 u = *(const uint2*)&g_x2h[(size_t)rr * C_HID + ch];
                float2 lo = __half22float2(*(__half2*)&u.x);
                float2 hi = __half22float2(*(__half2*)&u.y);
                x0 = relu6f(fmaf(lo.x, ssc[ch + 0], ssh[ch + 0]));
                x1 = relu6f(fmaf(lo.y, ssc[ch + 1], ssh[ch + 1]));
                x2 = relu6f(fmaf(hi.x, ssc[ch + 2], ssh[ch + 2]));
                x3 = relu6f(fmaf(hi.y, ssc[ch + 3], ssh[ch + 3]));
            }
            int kl = kq * 4;
            sxT[kl + 0][r] = x0;
            sxT[kl + 1][r] = x1;
            sxT[kl + 2][r] = x2;
            sxT[kl + 3][r] = x3;
        }
        __syncthreads();
#pragma unroll
        for (int k = 0; k < KC5; k++) {
            float4 w = *(const float4*)&sw3[(kc + k) * C_OUT + cb];
            float4 x = *(const float4*)&sxT[k][r0];
            float xr[4] = {x.x, x.y, x.z, x.w};
#pragma unroll
            for (int j = 0; j < 4; j++) {
                acc[j].x = fmaf(w.x, xr[j], acc[j].x);
                acc[j].y = fmaf(w.y, xr[j], acc[j].y);
                acc[j].z = fmaf(w.z, xr[j], acc[j].z);
                acc[j].w = fmaf(w.w, xr[j], acc[j].w);
            }
        }
    }

    float4 s4 = make_float4(0.f, 0.f, 0.f, 0.f), q4 = s4;
#pragma unroll
    for (int j = 0; j < 4; j++) {
        int rr = row0 + r0 + j;
        if (rr < N_PTS) {
            *(float4*)&g_y[(size_t)rr * C_OUT + cb] = acc[j];
            s4.x += acc[j].x; s4.y += acc[j].y; s4.z += acc[j].z; s4.w += acc[j].w;
            q4.x += acc[j].x * acc[j].x; q4.y += acc[j].y * acc[j].y;
            q4.z += acc[j].z * acc[j].z; q4.w += acc[j].w * acc[j].w;
        }
    }
    *(float4*)&rs[rg][cb] = s4;
    *(float4*)&rq[rg][cb] = q4;
    __syncthreads();
    if (tid < C_OUT) {
        float s = 0.f, q = 0.f;
#pragma unroll
        for (int g = 0; g < 32; g++) { s += rs[g][tid]; q += rq[g][tid]; }
        atomicAdd(&g_s3[tid], s);
        atomicAdd(&g_q3[tid], q);
    }
}

// ---- K7: out = bn3(y) + feats (float4); block0 zeroes stage-1 accumulators ----
__global__ void k7_out(const float* __restrict__ feats, float* __restrict__ out,
                       const float* __restrict__ g3, const float* __restrict__ b3) {
    __shared__ float ssc[C_OUT], ssh[C_OUT];
    int tid = threadIdx.x;
    if (blockIdx.x == 0 && tid < C_HID) { g_s1[tid] = 0.f; g_q1[tid] = 0.f; }
    if (tid < C_OUT) {
        float m = g_s3[tid] * (1.0f / N_PTS);
        float v = g_q3[tid] * (1.0f / N_PTS) - m * m;
        float sc = g3[tid] * rsqrtf(v + EPS);
        ssc[tid] = sc;
        ssh[tid] = b3[tid] - m * sc;
    }
    __syncthreads();

    int i = blockIdx.x * blockDim.x + tid;   // float4 index
    if (i < N_PTS * C_OUT / 4) {
        int cb = (i % 6) * 4;
        float4 y  = *(const float4*)&g_y[i * 4];
        float4 f  = *(const float4*)&feats[i * 4];
        float4 o;
        o.x = fmaf(y.x, ssc[cb + 0], ssh[cb + 0]) + f.x;
        o.y = fmaf(y.y, ssc[cb + 1], ssh[cb + 1]) + f.y;
        o.z = fmaf(y.z, ssc[cb + 2], ssh[cb + 2]) + f.z;
        o.w = fmaf(y.w, ssc[cb + 3], ssh[cb + 3]) + f.w;
        *(float4*)&out[i * 4] = o;
    }
}

extern "C" void kernel_launch(void* const* d_in, const int* in_sizes, int n_in,
                              void* d_out, int out_size) {
    const float* feats = (const float*)d_in[0];
    const float* w1    = (const float*)d_in[1];
    const float* g1    = (const float*)d_in[2];
    const float* b1    = (const float*)d_in[3];
    const float* w2    = (const float*)d_in[4];
    const float* g2    = (const float*)d_in[5];
    const float* b2    = (const float*)d_in[6];
    const float* w3    = (const float*)d_in[7];
    const float* g3    = (const float*)d_in[8];
    const float* b3    = (const float*)d_in[9];
    const int*   in_idx = (const int*)d_in[10];
    float* out = (float*)d_out;

    int nb1 = (N_PTS + R1 - 1) / R1;
    k1_gemm1<<<nb1, T1>>>(feats, w1);

    size_t total2 = (size_t)N_PTS * C_HID / 4;
    k2_act<<<(unsigned)((total2 + T2 - 1) / T2), T2>>>(g1, b1);

    int nb3 = (N_PTS + R3 - 1) / R3;
    k3_conv<<<nb3, T3>>>(w2, in_idx);

    int nb5 = (N_PTS + R5 - 1) / R5;
    k5_gemm3<<<nb5, T5>>>(w3, g2, b2);

    int total4 = N_PTS * C_OUT / 4;
    k7_out<<<(total4 + 255) / 256, 256>>>(feats, out, g3, b3);
}

// round 8
// speedup vs baseline: 1.3654x; 1.0433x over previous
#include <cuda_runtime.h>
#include <cuda_fp16.h>

#define N_PTS 100000
#define C_IN 24
#define C_HID 144
#define C_OUT 24
#define KS 9
#define EPS 1e-5f

// ---- scratch (device globals: allocation-free rule) ----
__device__ __align__(16) __half g_x1h[(N_PTS + 1) * C_HID];
__device__ __align__(16) __half g_x2h[N_PTS * C_HID];
__device__ __align__(16) float  g_y [N_PTS * C_OUT];

__device__ float g_s1[C_HID], g_q1[C_HID];
__device__ float g_s2[C_HID], g_q2[C_HID];
__device__ float g_s3[C_OUT], g_q3[C_OUT];

__device__ __forceinline__ float relu6f(float x) { return fminf(fmaxf(x, 0.f), 6.f); }

// ---- K1: x1 = feats @ w1 (fp16 out, fp32 stats); block0 zeroes stage-2 accums ----
#define R1 64
#define T1 288
__global__ void __launch_bounds__(T1) k1_gemm1(const float* __restrict__ feats,
                                               const float* __restrict__ w1) {
    __shared__ __align__(16) float sfT[C_IN][R1];
    __shared__ __align__(16) float sw1[C_IN * C_HID];
    __shared__ __align__(16) float rs[8][C_HID], rq[8][C_HID];

    int tid = threadIdx.x;
    int row0 = blockIdx.x * R1;

    if (blockIdx.x == 0 && tid < C_HID) { g_s2[tid] = 0.f; g_q2[tid] = 0.f; }

    for (int i = tid; i < C_IN * C_HID; i += T1) sw1[i] = w1[i];
    for (int i = tid; i < R1 * C_IN; i += T1) {
        int r = i / C_IN, k = i % C_IN;
        int rr = row0 + r;
        sfT[k][r] = (rr < N_PTS) ? feats[rr * C_IN + k] : 0.f;
    }
    __syncthreads();

    int c4 = tid % 36, rg = tid / 36;
    int cb = c4 * 4;
    float4 acc[8];
#pragma unroll
    for (int j = 0; j < 8; j++) acc[j] = make_float4(0.f, 0.f, 0.f, 0.f);

#pragma unroll
    for (int k = 0; k < C_IN; k++) {
        float4 w  = *(const float4*)&sw1[k * C_HID + cb];
        float4 xa = *(const float4*)&sfT[k][rg * 8];
        float4 xb = *(const float4*)&sfT[k][rg * 8 + 4];
        float xr[8] = {xa.x, xa.y, xa.z, xa.w, xb.x, xb.y, xb.z, xb.w};
#pragma unroll
        for (int j = 0; j < 8; j++) {
            acc[j].x = fmaf(w.x, xr[j], acc[j].x);
            acc[j].y = fmaf(w.y, xr[j], acc[j].y);
            acc[j].z = fmaf(w.z, xr[j], acc[j].z);
            acc[j].w = fmaf(w.w, xr[j], acc[j].w);
        }
    }

    float4 s4 = make_float4(0.f, 0.f, 0.f, 0.f), q4 = s4;
#pragma unroll
    for (int j = 0; j < 8; j++) {
        int rr = row0 + rg * 8 + j;
        if (rr < N_PTS) {
            __half2 h0 = __floats2half2_rn(acc[j].x, acc[j].y);
            __half2 h1 = __floats2half2_rn(acc[j].z, acc[j].w);
            uint2 pk;
            pk.x = *(unsigned int*)&h0;
            pk.y = *(unsigned int*)&h1;
            *(uint2*)&g_x1h[(size_t)rr * C_HID + cb] = pk;
        }
        s4.x += acc[j].x; s4.y += acc[j].y; s4.z += acc[j].z; s4.w += acc[j].w;
        q4.x += acc[j].x * acc[j].x; q4.y += acc[j].y * acc[j].y;
        q4.z += acc[j].z * acc[j].z; q4.w += acc[j].w * acc[j].w;
    }
    *(float4*)&rs[rg][cb] = s4;
    *(float4*)&rq[rg][cb] = q4;
    __syncthreads();
    if (tid < C_HID) {
        float s = 0.f, q = 0.f;
#pragma unroll
        for (int g = 0; g < 8; g++) { s += rs[g][tid]; q += rq[g][tid]; }
        atomicAdd(&g_s1[tid], s);
        atomicAdd(&g_q1[tid], q);
    }
}

// ---- K2: in-place activation x1 <- relu6(bn1(x1)), fp16 ----
#define T2 256
__global__ void __launch_bounds__(T2) k2_act(const float* __restrict__ g1,
                                             const float* __restrict__ b1) {
    __shared__ float ssc[C_HID], ssh[C_HID];
    int tid = threadIdx.x;
    if (tid < C_HID) {
        float m = g_s1[tid] * (1.0f / N_PTS);
        float v = g_q1[tid] * (1.0f / N_PTS) - m * m;
        float sc = g1[tid] * rsqrtf(v + EPS);
        ssc[tid] = sc;
        ssh[tid] = b1[tid] - m * sc;
    }
    __syncthreads();

    size_t i = (size_t)blockIdx.x * T2 + tid;        // uint2 = 4 halfs
    const size_t total = (size_t)N_PTS * C_HID / 4;
    if (i < total) {
        int ch = (int)((i * 4) % C_HID);
        uint2 u = *(const uint2*)&g_x1h[i * 4];
        float2 lo = __half22float2(*(__half2*)&u.x);
        float2 hi = __half22float2(*(__half2*)&u.y);
        float v0 = relu6f(fmaf(lo.x, ssc[ch + 0], ssh[ch + 0]));
        float v1 = relu6f(fmaf(lo.y, ssc[ch + 1], ssh[ch + 1]));
        float v2 = relu6f(fmaf(hi.x, ssc[ch + 2], ssh[ch + 2]));
        float v3 = relu6f(fmaf(hi.y, ssc[ch + 3], ssh[ch + 3]));
        __half2 h0 = __floats2half2_rn(v0, v1);
        __half2 h1 = __floats2half2_rn(v2, v3);
        uint2 pk;
        pk.x = *(unsigned int*)&h0;
        pk.y = *(unsigned int*)&h1;
        *(uint2*)&g_x1h[i * 4] = pk;
    }
}

// ---- K3: pure weighted gather conv + BN2 stats ----
#define R3 64
#define T3 288
__global__ void __launch_bounds__(T3) k3_conv(const float* __restrict__ w2,
                                              const int* __restrict__ in_idx) {
    __shared__ int snbr[R3][KS];
    __shared__ __align__(8) float rs[4][C_HID], rq[4][C_HID];

    int tid = threadIdx.x;
    int row0 = blockIdx.x * R3;

    if (blockIdx.x == 0 && tid < C_OUT) { g_s3[tid] = 0.f; g_q3[tid] = 0.f; }

#pragma unroll
    for (int t = 0; t < 2; t++) {
        int i = tid + t * T3;
        int k = i / R3, r = i % R3;
        int rr = row0 + r;
        snbr[r][k] = (rr < N_PTS) ? in_idx[k * N_PTS + rr] : N_PTS;
    }
    __syncthreads();

    int cg = tid % 72, rl = tid / 72;
    int cb = cg * 2;

    float2 wk[KS];
#pragma unroll
    for (int k = 0; k < KS; k++) wk[k] = *(const float2*)&w2[k * C_HID + cb];

    float s0 = 0.f, s1 = 0.f, q0 = 0.f, q1 = 0.f;
#pragma unroll 2
    for (int j = 0; j < 16; j++) {
        int r = rl * 16 + j;
        unsigned int h[KS];
#pragma unroll
        for (int k = 0; k < KS; k++)
            h[k] = *(const unsigned int*)&g_x1h[snbr[r][k] * C_HID + cb];

        float a0 = 0.f, a1 = 0.f;
#pragma unroll
        for (int k = 0; k < KS; k++) {
            float2 x = __half22float2(*(__half2*)&h[k]);
            a0 = fmaf(wk[k].x, x.x, a0);
            a1 = fmaf(wk[k].y, x.y, a1);
        }
        int rr = row0 + r;
        if (rr < N_PTS) {
            __half2 hh = __floats2half2_rn(a0, a1);
            *(unsigned int*)&g_x2h[(size_t)rr * C_HID + cb] = *(unsigned int*)&hh;
            s0 += a0; q0 += a0 * a0;
            s1 += a1; q1 += a1 * a1;
        }
    }
    rs[rl][cb] = s0; rs[rl][cb + 1] = s1;
    rq[rl][cb] = q0; rq[rl][cb + 1] = q1;
    __syncthreads();
    if (tid < C_HID) {
        float s = rs[0][tid] + rs[1][tid] + rs[2][tid] + rs[3][tid];
        float q = rq[0][tid] + rq[1][tid] + rq[2][tid] + rq[3][tid];
        atomicAdd(&g_s2[tid], s);
        atomicAdd(&g_q2[tid], q);
    }
}

// ---- K5: y = relu6(bn2(x2)) @ w3 + BN3 stats; 8 rows x 4 cols per thread ----
#define R5 256
#define T5 192
#define KC5 36
__global__ void __launch_bounds__(T5) k5_gemm3(const float* __restrict__ w3,
                                               const float* __restrict__ g2,
                                               const float* __restrict__ b2) {
    __shared__ __align__(16) float sxT[KC5][R5 + 4];
    __shared__ __align__(16) float sw3[C_HID * C_OUT];
    __shared__ __align__(16) float rs[32][C_OUT], rq[32][C_OUT];
    __shared__ float ssc[C_HID], ssh[C_HID];

    int tid = threadIdx.x;
    int row0 = blockIdx.x * R5;

    for (int i = tid; i < C_HID * C_OUT; i += T5) sw3[i] = w3[i];
    if (tid < C_HID) {
        float m = g_s2[tid] * (1.0f / N_PTS);
        float v = g_q2[tid] * (1.0f / N_PTS) - m * m;
        float sc = g2[tid] * rsqrtf(v + EPS);
        ssc[tid] = sc;
        ssh[tid] = b2[tid] - m * sc;
    }

    int c4 = tid % 6, rg = tid / 6;    // cols c4*4..+3, rows rg*8..+7 (rg 0..31)
    int cb = c4 * 4;
    int r0 = rg * 8;
    float4 acc[8];
#pragma unroll
    for (int j = 0; j < 8; j++) acc[j] = make_float4(0.f, 0.f, 0.f, 0.f);

    for (int kc = 0; kc < C_HID; kc += KC5) {
        __syncthreads();
        // stage KC5 channels x R5 rows; uint2 = 4 halfs per load
        for (int i = tid; i < (KC5 / 4) * R5; i += T5) {
            int r = i / 9, kq = i % 9;
            int rr = row0 + r;
            float x0 = 0.f, x1 = 0.f, x2 = 0.f, x3 = 0.f;
            int ch = kc + kq * 4;
            if (rr < N_PTS) {
                uint2 u = *(const uint2*)&g_x2h[(size_t)rr * C_HID + ch];
                float2 lo = __half22float2(*(__half2*)&u.x);
                float2 hi = __half22float2(*(__half2*)&u.y);
                x0 = relu6f(fmaf(lo.x, ssc[ch + 0], ssh[ch + 0]));
                x1 = relu6f(fmaf(lo.y, ssc[ch + 1], ssh[ch + 1]));
                x2 = relu6f(fmaf(hi.x, ssc[ch + 2], ssh[ch + 2]));
                x3 = relu6f(fmaf(hi.y, ssc[ch + 3], ssh[ch + 3]));
            }
            int kl = kq * 4;
            sxT[kl + 0][r] = x0;
            sxT[kl + 1][r] = x1;
            sxT[kl + 2][r] = x2;
            sxT[kl + 3][r] = x3;
        }
        __syncthreads();
#pragma unroll
        for (int k = 0; k < KC5; k++) {
            float4 w  = *(const float4*)&sw3[(kc + k) * C_OUT + cb];
            float4 xa = *(const float4*)&sxT[k][r0];
            float4 xb = *(const float4*)&sxT[k][r0 + 4];
            float xr[8] = {xa.x, xa.y, xa.z, xa.w, xb.x, xb.y, xb.z, xb.w};
#pragma unroll
            for (int j = 0; j < 8; j++) {
                acc[j].x = fmaf(w.x, xr[j], acc[j].x);
                acc[j].y = fmaf(w.y, xr[j], acc[j].y);
                acc[j].z = fmaf(w.z, xr[j], acc[j].z);
                acc[j].w = fmaf(w.w, xr[j], acc[j].w);
            }
        }
    }

    float4 s4 = make_float4(0.f, 0.f, 0.f, 0.f), q4 = s4;
#pragma unroll
    for (int j = 0; j < 8; j++) {
        int rr = row0 + r0 + j;
        if (rr < N_PTS) {
            *(float4*)&g_y[(size_t)rr * C_OUT + cb] = acc[j];
            s4.x += acc[j].x; s4.y += acc[j].y; s4.z += acc[j].z; s4.w += acc[j].w;
            q4.x += acc[j].x * acc[j].x; q4.y += acc[j].y * acc[j].y;
            q4.z += acc[j].z * acc[j].z; q4.w += acc[j].w * acc[j].w;
        }
    }
    *(float4*)&rs[rg][cb] = s4;
    *(float4*)&rq[rg][cb] = q4;
    __syncthreads();
    if (tid < C_OUT) {
        float s = 0.f, q = 0.f;
#pragma unroll
        for (int g = 0; g < 32; g++) { s += rs[g][tid]; q += rq[g][tid]; }
        atomicAdd(&g_s3[tid], s);
        atomicAdd(&g_q3[tid], q);
    }
}

// ---- K7: out = bn3(y) + feats (float4); block0 zeroes stage-1 accumulators ----
__global__ void k7_out(const float* __restrict__ feats, float* __restrict__ out,
                       const float* __restrict__ g3, const float* __restrict__ b3) {
    __shared__ float ssc[C_OUT], ssh[C_OUT];
    int tid = threadIdx.x;
    if (blockIdx.x == 0 && tid < C_HID) { g_s1[tid] = 0.f; g_q1[tid] = 0.f; }
    if (tid < C_OUT) {
        float m = g_s3[tid] * (1.0f / N_PTS);
        float v = g_q3[tid] * (1.0f / N_PTS) - m * m;
        float sc = g3[tid] * rsqrtf(v + EPS);
        ssc[tid] = sc;
        ssh[tid] = b3[tid] - m * sc;
    }
    __syncthreads();

    int i = blockIdx.x * blockDim.x + tid;   // float4 index
    if (i < N_PTS * C_OUT / 4) {
        int cb = (i % 6) * 4;
        float4 y  = *(const float4*)&g_y[i * 4];
        float4 f  = *(const float4*)&feats[i * 4];
        float4 o;
        o.x = fmaf(y.x, ssc[cb + 0], ssh[cb + 0]) + f.x;
        o.y = fmaf(y.y, ssc[cb + 1], ssh[cb + 1]) + f.y;
        o.z = fmaf(y.z, ssc[cb + 2], ssh[cb + 2]) + f.z;
        o.w = fmaf(y.w, ssc[cb + 3], ssh[cb + 3]) + f.w;
        *(float4*)&out[i * 4] = o;
    }
}

extern "C" void kernel_launch(void* const* d_in, const int* in_sizes, int n_in,
                              void* d_out, int out_size) {
    const float* feats = (const float*)d_in[0];
    const float* w1    = (const float*)d_in[1];
    const float* g1    = (const float*)d_in[2];
    const float* b1    = (const float*)d_in[3];
    const float* w2    = (const float*)d_in[4];
    const float* g2    = (const float*)d_in[5];
    const float* b2    = (const float*)d_in[6];
    const float* w3    = (const float*)d_in[7];
    const float* g3    = (const float*)d_in[8];
    const float* b3    = (const float*)d_in[9];
    const int*   in_idx = (const int*)d_in[10];
    float* out = (float*)d_out;

    int nb1 = (N_PTS + R1 - 1) / R1;
    k1_gemm1<<<nb1, T1>>>(feats, w1);

    size_t total2 = (size_t)N_PTS * C_HID / 4;
    k2_act<<<(unsigned)((total2 + T2 - 1) / T2), T2>>>(g1, b1);

    int nb3 = (N_PTS + R3 - 1) / R3;
    k3_conv<<<nb3, T3>>>(w2, in_idx);

    int nb5 = (N_PTS + R5 - 1) / R5;
    k5_gemm3<<<nb5, T5>>>(w3, g2, b2);

    int total4 = N_PTS * C_OUT / 4;
    k7_out<<<(total4 + 255) / 256, 256>>>(feats, out, g3, b3);
}

// round 9
// speedup vs baseline: 1.5697x; 1.1496x over previous
#include <cuda_runtime.h>
#include <cuda_fp16.h>

#define N_PTS 100000
#define C_IN 24
#define C_HID 144
#define C_OUT 24
#define KS 9
#define EPS 1e-5f

// ---- scratch (device globals: allocation-free rule) ----
__device__ __align__(16) __half g_x1h[(N_PTS + 1) * C_HID];
__device__ __align__(16) __half g_x2h[N_PTS * C_HID];
__device__ __align__(16) float  g_y [N_PTS * C_OUT];

__device__ float g_s1[C_HID], g_q1[C_HID];
__device__ float g_s2[C_HID], g_q2[C_HID];
__device__ float g_s3[C_OUT], g_q3[C_OUT];

__device__ __forceinline__ float relu6f(float x) { return fminf(fmaxf(x, 0.f), 6.f); }

__device__ __forceinline__ void mma16816(float* d,
                                         unsigned a0, unsigned a1, unsigned a2, unsigned a3,
                                         unsigned b0, unsigned b1) {
    asm volatile("mma.sync.aligned.m16n8k16.row.col.f32.f16.f16.f32 "
                 "{%0,%1,%2,%3}, {%4,%5,%6,%7}, {%8,%9}, {%0,%1,%2,%3};\n"
                 : "+f"(d[0]), "+f"(d[1]), "+f"(d[2]), "+f"(d[3])
                 : "r"(a0), "r"(a1), "r"(a2), "r"(a3), "r"(b0), "r"(b1));
}

// ---- K1: x1 = feats @ w1 (fp16 out, fp32 stats); block0 zeroes stage-2 accums ----
#define R1 64
#define T1 288
__global__ void __launch_bounds__(T1) k1_gemm1(const float* __restrict__ feats,
                                               const float* __restrict__ w1) {
    __shared__ __align__(16) float sfT[C_IN][R1];
    __shared__ __align__(16) float sw1[C_IN * C_HID];
    __shared__ __align__(16) float rs[8][C_HID], rq[8][C_HID];

    int tid = threadIdx.x;
    int row0 = blockIdx.x * R1;

    if (blockIdx.x == 0 && tid < C_HID) { g_s2[tid] = 0.f; g_q2[tid] = 0.f; }

    for (int i = tid; i < C_IN * C_HID; i += T1) sw1[i] = w1[i];
    for (int i = tid; i < R1 * C_IN; i += T1) {
        int r = i / C_IN, k = i % C_IN;
        int rr = row0 + r;
        sfT[k][r] = (rr < N_PTS) ? feats[rr * C_IN + k] : 0.f;
    }
    __syncthreads();

    int c4 = tid % 36, rg = tid / 36;
    int cb = c4 * 4;
    float4 acc[8];
#pragma unroll
    for (int j = 0; j < 8; j++) acc[j] = make_float4(0.f, 0.f, 0.f, 0.f);

#pragma unroll
    for (int k = 0; k < C_IN; k++) {
        float4 w  = *(const float4*)&sw1[k * C_HID + cb];
        float4 xa = *(const float4*)&sfT[k][rg * 8];
        float4 xb = *(const float4*)&sfT[k][rg * 8 + 4];
        float xr[8] = {xa.x, xa.y, xa.z, xa.w, xb.x, xb.y, xb.z, xb.w};
#pragma unroll
        for (int j = 0; j < 8; j++) {
            acc[j].x = fmaf(w.x, xr[j], acc[j].x);
            acc[j].y = fmaf(w.y, xr[j], acc[j].y);
            acc[j].z = fmaf(w.z, xr[j], acc[j].z);
            acc[j].w = fmaf(w.w, xr[j], acc[j].w);
        }
    }

    float4 s4 = make_float4(0.f, 0.f, 0.f, 0.f), q4 = s4;
#pragma unroll
    for (int j = 0; j < 8; j++) {
        int rr = row0 + rg * 8 + j;
        if (rr < N_PTS) {
            __half2 h0 = __floats2half2_rn(acc[j].x, acc[j].y);
            __half2 h1 = __floats2half2_rn(acc[j].z, acc[j].w);
            uint2 pk;
            pk.x = *(unsigned int*)&h0;
            pk.y = *(unsigned int*)&h1;
            *(uint2*)&g_x1h[(size_t)rr * C_HID + cb] = pk;
        }
        s4.x += acc[j].x; s4.y += acc[j].y; s4.z += acc[j].z; s4.w += acc[j].w;
        q4.x += acc[j].x * acc[j].x; q4.y += acc[j].y * acc[j].y;
        q4.z += acc[j].z * acc[j].z; q4.w += acc[j].w * acc[j].w;
    }
    *(float4*)&rs[rg][cb] = s4;
    *(float4*)&rq[rg][cb] = q4;
    __syncthreads();
    if (tid < C_HID) {
        float s = 0.f, q = 0.f;
#pragma unroll
        for (int g = 0; g < 8; g++) { s += rs[g][tid]; q += rq[g][tid]; }
        atomicAdd(&g_s1[tid], s);
        atomicAdd(&g_q1[tid], q);
    }
}

// ---- K2: in-place activation x1 <- relu6(bn1(x1)), fp16 ----
#define T2 256
__global__ void __launch_bounds__(T2) k2_act(const float* __restrict__ g1,
                                             const float* __restrict__ b1) {
    __shared__ float ssc[C_HID], ssh[C_HID];
    int tid = threadIdx.x;
    if (tid < C_HID) {
        float m = g_s1[tid] * (1.0f / N_PTS);
        float v = g_q1[tid] * (1.0f / N_PTS) - m * m;
        float sc = g1[tid] * rsqrtf(v + EPS);
        ssc[tid] = sc;
        ssh[tid] = b1[tid] - m * sc;
    }
    __syncthreads();

    size_t i = (size_t)blockIdx.x * T2 + tid;        // uint2 = 4 halfs
    const size_t total = (size_t)N_PTS * C_HID / 4;
    if (i < total) {
        int ch = (int)((i * 4) % C_HID);
        uint2 u = *(const uint2*)&g_x1h[i * 4];
        float2 lo = __half22float2(*(__half2*)&u.x);
        float2 hi = __half22float2(*(__half2*)&u.y);
        float v0 = relu6f(fmaf(lo.x, ssc[ch + 0], ssh[ch + 0]));
        float v1 = relu6f(fmaf(lo.y, ssc[ch + 1], ssh[ch + 1]));
        float v2 = relu6f(fmaf(hi.x, ssc[ch + 2], ssh[ch + 2]));
        float v3 = relu6f(fmaf(hi.y, ssc[ch + 3], ssh[ch + 3]));
        __half2 h0 = __floats2half2_rn(v0, v1);
        __half2 h1 = __floats2half2_rn(v2, v3);
        uint2 pk;
        pk.x = *(unsigned int*)&h0;
        pk.y = *(unsigned int*)&h1;
        *(uint2*)&g_x1h[i * 4] = pk;
    }
}

// ---- K3: pure weighted gather conv + BN2 stats ----
#define R3 64
#define T3 288
__global__ void __launch_bounds__(T3) k3_conv(const float* __restrict__ w2,
                                              const int* __restrict__ in_idx) {
    __shared__ int snbr[R3][KS];
    __shared__ __align__(8) float rs[4][C_HID], rq[4][C_HID];

    int tid = threadIdx.x;
    int row0 = blockIdx.x * R3;

    if (blockIdx.x == 0 && tid < C_OUT) { g_s3[tid] = 0.f; g_q3[tid] = 0.f; }

#pragma unroll
    for (int t = 0; t < 2; t++) {
        int i = tid + t * T3;
        int k = i / R3, r = i % R3;
        int rr = row0 + r;
        snbr[r][k] = (rr < N_PTS) ? in_idx[k * N_PTS + rr] : N_PTS;
    }
    __syncthreads();

    int cg = tid % 72, rl = tid / 72;
    int cb = cg * 2;

    float2 wk[KS];
#pragma unroll
    for (int k = 0; k < KS; k++) wk[k] = *(const float2*)&w2[k * C_HID + cb];

    float s0 = 0.f, s1 = 0.f, q0 = 0.f, q1 = 0.f;
#pragma unroll 2
    for (int j = 0; j < 16; j++) {
        int r = rl * 16 + j;
        unsigned int h[KS];
#pragma unroll
        for (int k = 0; k < KS; k++)
            h[k] = *(const unsigned int*)&g_x1h[snbr[r][k] * C_HID + cb];

        float a0 = 0.f, a1 = 0.f;
#pragma unroll
        for (int k = 0; k < KS; k++) {
            float2 x = __half22float2(*(__half2*)&h[k]);
            a0 = fmaf(wk[k].x, x.x, a0);
            a1 = fmaf(wk[k].y, x.y, a1);
        }
        int rr = row0 + r;
        if (rr < N_PTS) {
            __half2 hh = __floats2half2_rn(a0, a1);
            *(unsigned int*)&g_x2h[(size_t)rr * C_HID + cb] = *(unsigned int*)&hh;
            s0 += a0; q0 += a0 * a0;
            s1 += a1; q1 += a1 * a1;
        }
    }
    rs[rl][cb] = s0; rs[rl][cb + 1] = s1;
    rq[rl][cb] = q0; rq[rl][cb + 1] = q1;
    __syncthreads();
    if (tid < C_HID) {
        float s = rs[0][tid] + rs[1][tid] + rs[2][tid] + rs[3][tid];
        float q = rq[0][tid] + rq[1][tid] + rq[2][tid] + rq[3][tid];
        atomicAdd(&g_s2[tid], s);
        atomicAdd(&g_q2[tid], q);
    }
}

// ---- K4: in-place activation x2 <- relu6(bn2(x2)), fp16 ----
__global__ void __launch_bounds__(T2) k4_act(const float* __restrict__ g2,
                                             const float* __restrict__ b2) {
    __shared__ float ssc[C_HID], ssh[C_HID];
    int tid = threadIdx.x;
    if (tid < C_HID) {
        float m = g_s2[tid] * (1.0f / N_PTS);
        float v = g_q2[tid] * (1.0f / N_PTS) - m * m;
        float sc = g2[tid] * rsqrtf(v + EPS);
        ssc[tid] = sc;
        ssh[tid] = b2[tid] - m * sc;
    }
    __syncthreads();

    size_t i = (size_t)blockIdx.x * T2 + tid;        // uint2 = 4 halfs
    const size_t total = (size_t)N_PTS * C_HID / 4;
    if (i < total) {
        int ch = (int)((i * 4) % C_HID);
        uint2 u = *(const uint2*)&g_x2h[i * 4];
        float2 lo = __half22float2(*(__half2*)&u.x);
        float2 hi = __half22float2(*(__half2*)&u.y);
        float v0 = relu6f(fmaf(lo.x, ssc[ch + 0], ssh[ch + 0]));
        float v1 = relu6f(fmaf(lo.y, ssc[ch + 1], ssh[ch + 1]));
        float v2 = relu6f(fmaf(hi.x, ssc[ch + 2], ssh[ch + 2]));
        float v3 = relu6f(fmaf(hi.y, ssc[ch + 3], ssh[ch + 3]));
        __half2 h0 = __floats2half2_rn(v0, v1);
        __half2 h1 = __floats2half2_rn(v2, v3);
        uint2 pk;
        pk.x = *(unsigned int*)&h0;
        pk.y = *(unsigned int*)&h1;
        *(uint2*)&g_x2h[i * 4] = pk;
    }
}

// ---- K5: y = x2_act @ w3 via mma.m16n8k16 + BN3 stats ----
// 4 warps/block; each warp: 4 m16 tiles (64 rows) x 3 n8 tiles. 256 rows/block.
#define T5 128
#define R5T 256
__global__ void __launch_bounds__(T5) k5_tc(const float* __restrict__ w3) {
    __shared__ __align__(4) unsigned int swp[72 * C_OUT];   // half2 (k,k+1) pairs
    __shared__ float ssum[C_OUT], ssq[C_OUT];

    int tid = threadIdx.x;
    int lane = tid & 31, wid = tid >> 5;
    int g = lane >> 2, c = lane & 3;

    for (int i = tid; i < 72 * C_OUT; i += T5) {
        int kk = i / C_OUT, n = i % C_OUT;
        __half2 h = __floats2half2_rn(w3[(2 * kk) * C_OUT + n],
                                      w3[(2 * kk + 1) * C_OUT + n]);
        swp[i] = *(unsigned int*)&h;
    }
    if (tid < C_OUT) { ssum[tid] = 0.f; ssq[tid] = 0.f; }
    __syncthreads();

    int row0 = blockIdx.x * R5T + wid * 64;

    float acc[4][3][4];
#pragma unroll
    for (int mt = 0; mt < 4; mt++)
#pragma unroll
        for (int nt = 0; nt < 3; nt++)
#pragma unroll
            for (int j = 0; j < 4; j++) acc[mt][nt][j] = 0.f;

#pragma unroll
    for (int ks = 0; ks < 9; ks++) {
        int k0 = ks * 16;
        unsigned int b[3][2];
        int kb = (k0 >> 1) + c;
#pragma unroll
        for (int nt = 0; nt < 3; nt++) {
            int n = nt * 8 + g;
            b[nt][0] = swp[kb * C_OUT + n];
            b[nt][1] = swp[(kb + 4) * C_OUT + n];
        }
#pragma unroll
        for (int mt = 0; mt < 4; mt++) {
            int r  = row0 + mt * 16 + g;
            int rA = min(r, N_PTS - 1);
            int rB = min(r + 8, N_PTS - 1);
            unsigned int a0 = *(const unsigned int*)&g_x2h[(size_t)rA * C_HID + k0 + 2 * c];
            unsigned int a1 = *(const unsigned int*)&g_x2h[(size_t)rB * C_HID + k0 + 2 * c];
            unsigned int a2 = *(const unsigned int*)&g_x2h[(size_t)rA * C_HID + k0 + 2 * c + 8];
            unsigned int a3 = *(const unsigned int*)&g_x2h[(size_t)rB * C_HID + k0 + 2 * c + 8];
#pragma unroll
            for (int nt = 0; nt < 3; nt++)
                mma16816(acc[mt][nt], a0, a1, a2, a3, b[nt][0], b[nt][1]);
        }
    }

    // epilogue: store y + per-column stats
    float s[3][2], q[3][2];
#pragma unroll
    for (int nt = 0; nt < 3; nt++) { s[nt][0] = s[nt][1] = 0.f; q[nt][0] = q[nt][1] = 0.f; }

#pragma unroll
    for (int mt = 0; mt < 4; mt++) {
        int r = row0 + mt * 16 + g;
#pragma unroll
        for (int nt = 0; nt < 3; nt++) {
            int n = nt * 8 + 2 * c;
            if (r < N_PTS) {
                float c0 = acc[mt][nt][0], c1 = acc[mt][nt][1];
                *(float2*)&g_y[(size_t)r * C_OUT + n] = make_float2(c0, c1);
                s[nt][0] += c0; q[nt][0] += c0 * c0;
                s[nt][1] += c1; q[nt][1] += c1 * c1;
            }
            if (r + 8 < N_PTS) {
                float c2 = acc[mt][nt][2], c3 = acc[mt][nt][3];
                *(float2*)&g_y[(size_t)(r + 8) * C_OUT + n] = make_float2(c2, c3);
                s[nt][0] += c2; q[nt][0] += c2 * c2;
                s[nt][1] += c3; q[nt][1] += c3 * c3;
            }
        }
    }
    // reduce over g (lane bits 2..4)
#pragma unroll
    for (int off = 16; off >= 4; off >>= 1) {
#pragma unroll
        for (int nt = 0; nt < 3; nt++) {
#pragma unroll
            for (int j = 0; j < 2; j++) {
                s[nt][j] += __shfl_down_sync(0xffffffffu, s[nt][j], off);
                q[nt][j] += __shfl_down_sync(0xffffffffu, q[nt][j], off);
            }
        }
    }
    if (g == 0) {
#pragma unroll
        for (int nt = 0; nt < 3; nt++) {
            int n = nt * 8 + 2 * c;
            atomicAdd(&ssum[n],     s[nt][0]);
            atomicAdd(&ssum[n + 1], s[nt][1]);
            atomicAdd(&ssq[n],      q[nt][0]);
            atomicAdd(&ssq[n + 1],  q[nt][1]);
        }
    }
    __syncthreads();
    if (tid < C_OUT) {
        atomicAdd(&g_s3[tid], ssum[tid]);
        atomicAdd(&g_q3[tid], ssq[tid]);
    }
}

// ---- K7: out = bn3(y) + feats (float4); block0 zeroes stage-1 accumulators ----
__global__ void k7_out(const float* __restrict__ feats, float* __restrict__ out,
                       const float* __restrict__ g3, const float* __restrict__ b3) {
    __shared__ float ssc[C_OUT], ssh[C_OUT];
    int tid = threadIdx.x;
    if (blockIdx.x == 0 && tid < C_HID) { g_s1[tid] = 0.f; g_q1[tid] = 0.f; }
    if (tid < C_OUT) {
        float m = g_s3[tid] * (1.0f / N_PTS);
        float v = g_q3[tid] * (1.0f / N_PTS) - m * m;
        float sc = g3[tid] * rsqrtf(v + EPS);
        ssc[tid] = sc;
        ssh[tid] = b3[tid] - m * sc;
    }
    __syncthreads();

    int i = blockIdx.x * blockDim.x + tid;   // float4 index
    if (i < N_PTS * C_OUT / 4) {
        int cb = (i % 6) * 4;
        float4 y  = *(const float4*)&g_y[i * 4];
        float4 f  = *(const float4*)&feats[i * 4];
        float4 o;
        o.x = fmaf(y.x, ssc[cb + 0], ssh[cb + 0]) + f.x;
        o.y = fmaf(y.y, ssc[cb + 1], ssh[cb + 1]) + f.y;
        o.z = fmaf(y.z, ssc[cb + 2], ssh[cb + 2]) + f.z;
        o.w = fmaf(y.w, ssc[cb + 3], ssh[cb + 3]) + f.w;
        *(float4*)&out[i * 4] = o;
    }
}

extern "C" void kernel_launch(void* const* d_in, const int* in_sizes, int n_in,
                              void* d_out, int out_size) {
    const float* feats = (const float*)d_in[0];
    const float* w1    = (const float*)d_in[1];
    const float* g1    = (const float*)d_in[2];
    const float* b1    = (const float*)d_in[3];
    const float* w2    = (const float*)d_in[4];
    const float* g2    = (const float*)d_in[5];
    const float* b2    = (const float*)d_in[6];
    const float* w3    = (const float*)d_in[7];
    const float* g3    = (const float*)d_in[8];
    const float* b3    = (const float*)d_in[9];
    const int*   in_idx = (const int*)d_in[10];
    float* out = (float*)d_out;

    int nb1 = (N_PTS + R1 - 1) / R1;
    k1_gemm1<<<nb1, T1>>>(feats, w1);

    size_t total2 = (size_t)N_PTS * C_HID / 4;
    k2_act<<<(unsigned)((total2 + T2 - 1) / T2), T2>>>(g1, b1);

    int nb3 = (N_PTS + R3 - 1) / R3;
    k3_conv<<<nb3, T3>>>(w2, in_idx);

    k4_act<<<(unsigned)((total2 + T2 - 1) / T2), T2>>>(g2, b2);

    int nb5 = (N_PTS + R5T - 1) / R5T;
    k5_tc<<<nb5, T5>>>(w3);

    int total4 = N_PTS * C_OUT / 4;
    k7_out<<<(total4 + 255) / 256, 256>>>(feats, out, g3, b3);
}